// round 15
// baseline (speedup 1.0000x reference)
#include <cuda_runtime.h>

// SRLEmbeddings: B=16,S=32,L=256,D=768,P=16,T=4, PAD=1
// Balanced warp-specialized kernel. Grid 1024 = (b*s) x 2 column halves.
// Block 384 = 192 stream threads (96 f4-groups x 2 row-lanes)
//           + 192 gather threads (48 pairs x 4 col-slices).
// Stream group: masked sentence sum over active rows (DRAM-bound).
// Gather group: 48 scanners build event lists, then each thread gathers its
//   (pair, 24-cg slice) with ~72 independent loads and writes results
//   directly to gmem. Groups share ONE __syncthreads, then run concurrently.

#define NB 16
#define NS 32
#define NL 256
#define ND 768
#define ND4 (ND / 4)
#define NP 16
#define NT 4
#define NPAIR 48
#define PAD_ID 1
#define EVCAP 16

#define NTHREADS 384
#define NSTREAM 192
#define HCG 96            // float4 col-groups per half

__global__ __launch_bounds__(NTHREADS, 5)
void srl_kernel(const int* __restrict__ sent_ids,
                const int* __restrict__ attn,
                const int* __restrict__ pred_ids,
                const int* __restrict__ arg0_ids,
                const int* __restrict__ arg1_ids,
                const float* __restrict__ emb,
                float* __restrict__ out)
{
    __shared__ int            sid_s[NL];
    __shared__ int            alist[NL];
    __shared__ int            span_s[NPAIR * NT];
    __shared__ unsigned short events[NPAIR * EVCAP];   // l | cnt<<8
    __shared__ int            nev[NPAIR];
    __shared__ float          inv_s[NPAIR];
    __shared__ float4         stage[2 * HCG];
    __shared__ int            nact_s;

    const int blk  = blockIdx.x;
    const int bs   = blk >> 1;
    const int half = blk & 1;
    const int tid  = threadIdx.x;
    const int lane = tid & 31;

    // ---- phase 0: metadata (all 384 threads) ----
    if (tid < NL) sid_s[tid] = sent_ids[bs * NL + tid];
    if (tid < NPAIR * NT) {   // 192 ints
        int arg = tid / (NP * NT);
        int rem = tid % (NP * NT);
        const int* src = (arg == 0) ? pred_ids : ((arg == 1) ? arg0_ids : arg1_ids);
        span_s[tid] = src[bs * NP * NT + rem];
    }
    if (tid < 32) {   // warp 0: ballot compaction (ascending, deterministic)
        int base = 0;
        #pragma unroll
        for (int c = 0; c < NL / 32; c++) {
            int l = c * 32 + lane;
            int a = attn[bs * NL + l];
            unsigned m = __ballot_sync(0xFFFFFFFFu, a != 0);
            if (a != 0) alist[base + __popc(m & ((1u << lane) - 1u))] = l;
            base += __popc(m);
        }
        if (lane == 0) nact_s = base;
    }
    __syncthreads();     // the ONLY block-wide barrier

    const int nact = nact_s;
    const float4* ebase = (const float4*)(emb + (size_t)bs * NL * ND) + half * HCG;

    if (tid < NSTREAM) {
        // ================= STREAM GROUP (6 warps) =================
        const int cg = tid % HCG;       // 0..95
        const int rl = tid / HCG;       // 0..1
        const float4* eb = ebase + cg;
        float4 s4 = make_float4(0.f, 0.f, 0.f, 0.f);
        const int clampi = nact - 1;

        #pragma unroll 1
        for (int i0 = 0; i0 < nact; i0 += 8) {
            float4 v[4];
            int    idx[4];
            #pragma unroll
            for (int k = 0; k < 4; k++) {
                idx[k] = i0 + 2 * k + rl;
                int ci = min(idx[k], clampi);
                int l  = alist[ci];
                v[k] = __ldg(eb + (size_t)l * ND4);
            }
            #pragma unroll
            for (int k = 0; k < 4; k++) {
                if (idx[k] < nact) {
                    s4.x += v[k].x; s4.y += v[k].y; s4.z += v[k].z; s4.w += v[k].w;
                }
            }
        }
        stage[rl * HCG + cg] = s4;
        asm volatile("bar.sync 1, %0;" :: "n"(NSTREAM) : "memory");

        if (rl == 0) {
            float4 a = stage[cg], b = stage[HCG + cg];
            float tc = fmaxf((float)nact, 1.0f);
            float4 o;
            o.x = (a.x + b.x) / tc;
            o.y = (a.y + b.y) / tc;
            o.z = (a.z + b.z) / tc;
            o.w = (a.w + b.w) / tc;
            ((float4*)(out + (size_t)bs * ND))[half * HCG + cg] = o;
        }
    } else {
        // ================= GATHER GROUP (6 warps) =================
        const int g     = tid - NSTREAM;   // 0..191
        const int pair  = g >> 2;          // 0..47
        const int slice = g & 3;           // 0..3  -> cg = slice + 4j

        // phase 1: 48 parallel scanners (one pair each, ascending order)
        if (slice == 0) {
            int v0 = span_s[pair * NT + 0];
            int v1 = span_s[pair * NT + 1];
            int v2 = span_s[pair * NT + 2];
            int v3 = span_s[pair * NT + 3];
            int n = 0, den = 0;
            #pragma unroll 1
            for (int i = 0; i < nact; i++) {
                int l = alist[i];
                int sid = sid_s[l];
                int c = (v0 == sid && v0 != PAD_ID)
                      + (v1 == sid && v1 != PAD_ID)
                      + (v2 == sid && v2 != PAD_ID)
                      + (v3 == sid && v3 != PAD_ID);
                if (c && n < EVCAP) {
                    events[pair * EVCAP + n++] = (unsigned short)(l | (c << 8));
                    den += c;
                }
            }
            nev[pair]   = n;
            inv_s[pair] = (den > 0) ? 1.0f / (float)den : 0.0f;
        }
        asm volatile("bar.sync 2, %0;" :: "n"(NTHREADS - NSTREAM) : "memory");

        const int   ne  = nev[pair];
        const float inv = inv_s[pair];
        const int   arg = pair >> 4;
        const int   p   = pair & 15;
        float4* o4 = (float4*)(out + (size_t)NB * NS * ND
                                   + (size_t)arg * NB * NS * NP * ND
                                   + (size_t)bs * NP * ND
                                   + (size_t)p * ND) + half * HCG;

        // gather: 24 cg per thread (cg = slice + 4j), events inner, unroll 2
        #pragma unroll 2
        for (int j = 0; j < 24; j++) {
            int cg = slice + 4 * j;
            float4 val = make_float4(0.f, 0.f, 0.f, 0.f);
            #pragma unroll 1
            for (int i = 0; i < ne; i++) {
                unsigned e = events[pair * EVCAP + i];
                int   l = (int)(e & 0xFFu);
                float c = (float)(e >> 8);
                float4 w = __ldg(ebase + (size_t)l * ND4 + cg);
                val.x = fmaf(c, w.x, val.x);
                val.y = fmaf(c, w.y, val.y);
                val.z = fmaf(c, w.z, val.z);
                val.w = fmaf(c, w.w, val.w);
            }
            o4[cg] = make_float4(val.x * inv, val.y * inv, val.z * inv, val.w * inv);
        }
    }
}

extern "C" void kernel_launch(void* const* d_in, const int* in_sizes, int n_in,
                              void* d_out, int out_size)
{
    const int*   sent_ids = (const int*)d_in[0];
    const int*   attn     = (const int*)d_in[1];
    const int*   pred_ids = (const int*)d_in[2];
    const int*   arg0_ids = (const int*)d_in[3];
    const int*   arg1_ids = (const int*)d_in[4];
    const float* emb      = (const float*)d_in[5];
    float*       out      = (float*)d_out;

    dim3 grid(NB * NS * 2);
    dim3 block(NTHREADS);
    srl_kernel<<<grid, block>>>(sent_ids, attn, pred_ids, arg0_ids,
                                arg1_ids, emb, out);
}